// round 14
// baseline (speedup 1.0000x reference)
#include <cuda_runtime.h>
#include <cuda_bf16.h>
#include <math.h>
#include <stdint.h>

#define NN_ 50000
#define GG_ 2500
#define PGRID 4096
#define INV_SQMZ 0.04419417382415922f

typedef unsigned long long ull;

// ---------------- device scratch ----------------
__device__ float g_sinv[(size_t)NN_ * 384];   // per-node invariant norms
__device__ float g_scov[(size_t)GG_ * 1152];  // focused-node cov vectors (with /SQ_MZ)
__device__ float g_fl[NN_];                   // focus logits
__device__ float g_el[(size_t)NN_ * 4];       // element logits
__device__ float g_Y[9 * PGRID];              // SH basis on Fibonacci grid, [j][p]
__device__ float g_lp12[GG_];                 // lp_focus + lp_element

__device__ __forceinline__ float wsum(float v) {
#pragma unroll
    for (int s = 16; s > 0; s >>= 1) v += __shfl_xor_sync(0xffffffffu, v, s);
    return v;
}

__device__ __forceinline__ ull pk2(float lo, float hi) {
    ull r;
    asm("mov.b64 %0, {%1, %2};" : "=l"(r) : "f"(lo), "f"(hi));
    return r;
}
__device__ __forceinline__ void upk2(ull v, float& lo, float& hi) {
    asm("mov.b64 {%0, %1}, %2;" : "=f"(lo), "=f"(hi) : "l"(v));
}
__device__ __forceinline__ void fma2_(ull& d, ull a, ull b) {
    asm("fma.rn.f32x2 %0, %1, %2, %0;" : "+l"(d) : "l"(a), "l"(b));
}
__device__ __forceinline__ unsigned int smem_u32(const void* p) {
    return (unsigned int)__cvta_generic_to_shared(p);
}
__device__ __forceinline__ void cpa16(unsigned int dst, const float* src) {
    asm volatile("cp.async.ca.shared.global [%0], [%1], 16;" :: "r"(dst), "l"(src));
}
#define CP_COMMIT() asm volatile("cp.async.commit_group;")
#define CP_WAIT(N)  asm volatile("cp.async.wait_group %0;" :: "n"(N))

// ---------------- K0: build Y_GRID ----------------
__global__ void k0_ygrid() {
    int i = blockIdx.x * blockDim.x + threadIdx.x;
    if (i >= PGRID) return;
    double ph = 3.14159265358979323846 * (3.0 - sqrt(5.0)) * (double)i;
    double z  = 1.0 - 2.0 * ((double)i + 0.5) / (double)PGRID;
    double rr = 1.0 - z * z; if (rr < 0.0) rr = 0.0;
    double r  = sqrt(rr);
    float x  = (float)(r * cos(ph));
    float y  = (float)(r * sin(ph));
    float zf = (float)z;
    g_Y[0 * PGRID + i] = 0.28209479177387814f;
    g_Y[1 * PGRID + i] = 0.4886025119029199f * y;
    g_Y[2 * PGRID + i] = 0.4886025119029199f * zf;
    g_Y[3 * PGRID + i] = 0.4886025119029199f * x;
    g_Y[4 * PGRID + i] = 1.0925484305920792f * x * y;
    g_Y[5 * PGRID + i] = 1.0925484305920792f * y * zf;
    g_Y[6 * PGRID + i] = 0.31539156525252005f * (3.f * zf * zf - 1.f);
    g_Y[7 * PGRID + i] = 1.0925484305920792f * x * zf;
    g_Y[8 * PGRID + i] = 0.5462742152960396f * (x * x - y * y);
}

// ---------------- K1: pipelined per-group cov GEMM + norms ----------------
// 320 threads: cq = tid&63 -> cols {2cq, 2cq+1}; nq = tid>>6 -> nodes 4nq..4nq+3.
// 8 chunks of 16 k. Raw W_bag (L2-resident) arrives via double-buffered
// cp.async; bag-fold into sW is a pipelined stage; X register-prefetched.
// NOTE: cp.async wait_group is PER-THREAD — a __syncthreads() must sit
// between CP_WAIT and any cross-thread read of the copied buffer.
template <int OL>
__device__ __forceinline__ void k1_compute(
    const float* __restrict__ sWb, const float* __restrict__ sXb,
    int cq, int nq, ull (&acc)[2][2][OL])
{
    const float* wp = sWb + cq * 2;
    const float* xp = sXb + nq * 4;
#pragma unroll 8
    for (int kk = 0; kk < 16; kk++) {
        const float2 w = *reinterpret_cast<const float2*>(wp + kk * 128);
        const ull wd0 = pk2(w.x, w.x);
        const ull wd1 = pk2(w.y, w.y);
#pragma unroll
        for (int m = 0; m < OL; m++) {
            const ulonglong2 xv = *reinterpret_cast<const ulonglong2*>(
                xp + (kk * OL + m) * 20);
            fma2_(acc[0][0][m], wd0, xv.x);
            fma2_(acc[0][1][m], wd0, xv.y);
            fma2_(acc[1][0][m], wd1, xv.x);
            fma2_(acc[1][1][m], wd1, xv.y);
        }
    }
}

template <int L>
__global__ void __launch_bounds__(320, 2) k1_cov(
    const float* __restrict__ s_inter, const float* __restrict__ bag,
    const int* __restrict__ ptr, const int* __restrict__ focus,
    const float* __restrict__ W_bag)
{
    constexpr int OL  = (L == 0) ? 1 : (L == 1 ? 3 : 5);
    constexpr int OFF = (L == 0) ? 0 : (L == 1 ? 128 : 512);
    constexpr int XCH = 16 * OL;    // floats per node per chunk
    constexpr int NPT = OL;         // X elements per thread per chunk (exact)

    __shared__ __align__(16) float sRaw[2][16 * 512];   // raw W_bag chunks
    __shared__ __align__(16) float sW[2][16 * 128];     // folded W_eff
    __shared__ __align__(16) float sX[2][OL * 16 * 20]; // [kk*OL+m][n]

    const int g   = blockIdx.x;
    const int tid = threadIdx.x;
    const int cq  = tid & 63;
    const int nq  = tid >> 6;
    const int n0  = ptr[g];
    const float b0 = bag[g * 4 + 0], b1 = bag[g * 4 + 1];
    const float b2 = bag[g * 4 + 2], b3 = bag[g * 4 + 3];
    const float* Wraw = W_bag + (size_t)L * 65536;
    const float* Xg   = s_inter + (size_t)n0 * 1152 + OFF;

    ull acc[2][2][OL];
#pragma unroll
    for (int cc = 0; cc < 2; cc++)
#pragma unroll
        for (int np = 0; np < 2; np++)
#pragma unroll
            for (int m = 0; m < OL; m++) acc[cc][np][m] = 0ull;

    float xr[NPT];

    // ---- raw W chunk -> smem via cp.async (32 KB contiguous) ----
#define CPRAW(C, B)                                                         \
    {                                                                       \
        const unsigned int d = smem_u32(&sRaw[B][0]);                       \
        const float* s = Wraw + (C) * 8192;                                 \
        for (int t = tid; t < 2048; t += 320) cpa16(d + t * 16, s + t * 4); \
        CP_COMMIT();                                                        \
    }
    // ---- fold raw chunk -> sW: sW[ii][o] = sum_z bag[z]*raw[ii][z][o] ----
#define FOLD(RB, WB)                                                        \
    {                                                                       \
        for (int t = tid; t < 512; t += 320) {                              \
            const int ii = t >> 5, o4 = (t & 31) << 2;                      \
            const float* rp = sRaw[RB] + ii * 512 + o4;                     \
            const float4 w0 = *reinterpret_cast<const float4*>(rp);         \
            const float4 w1 = *reinterpret_cast<const float4*>(rp + 128);   \
            const float4 w2 = *reinterpret_cast<const float4*>(rp + 256);   \
            const float4 w3 = *reinterpret_cast<const float4*>(rp + 384);   \
            float4 r;                                                       \
            r.x = fmaf(b0, w0.x, fmaf(b1, w1.x, fmaf(b2, w2.x, b3 * w3.x))); \
            r.y = fmaf(b0, w0.y, fmaf(b1, w1.y, fmaf(b2, w2.y, b3 * w3.y))); \
            r.z = fmaf(b0, w0.z, fmaf(b1, w1.z, fmaf(b2, w2.z, b3 * w3.z))); \
            r.w = fmaf(b0, w0.w, fmaf(b1, w1.w, fmaf(b2, w2.w, b3 * w3.w))); \
            *reinterpret_cast<float4*>(sW[WB] + ii * 128 + o4) = r;         \
        }                                                                   \
    }
    // ---- X chunk -> regs ----
#define LDX(C)                                                              \
    {                                                                       \
        const float* src = Xg + (C) * XCH;                                  \
        _Pragma("unroll")                                                   \
        for (int t = 0; t < NPT; t++) {                                     \
            const int idx = tid + t * 320;                                  \
            const int nl = idx / XCH;                                       \
            const int j  = idx - nl * XCH;                                  \
            xr[t] = src[(size_t)nl * 1152 + j];                             \
        }                                                                   \
    }
    // ---- X regs -> smem (transposed) ----
#define STX(B)                                                              \
    {                                                                       \
        _Pragma("unroll")                                                   \
        for (int t = 0; t < NPT; t++) {                                     \
            const int idx = tid + t * 320;                                  \
            const int nl = idx / XCH;                                       \
            const int j  = idx - nl * XCH;                                  \
            sX[B][j * 20 + nl] = xr[t];                                     \
        }                                                                   \
    }

    // ---- preamble ----
    CPRAW(0, 0);
    LDX(0);
    CPRAW(1, 1);
    CP_WAIT(1);            // this thread's raw0 copies done
    __syncthreads();       // ALL threads' raw0 copies done & visible
    STX(0);
    FOLD(0, 0);
    __syncthreads();       // sX0 + sW0 visible

    // ---- main loop, 8 chunks ----
#pragma unroll
    for (int c = 0; c < 8; c++) {
        const int cur = c & 1, nxt = cur ^ 1;
        if (c + 2 < 8) CPRAW(c + 2, cur);     // raw[cur] folded at end of c-1, synced
        if (c + 1 < 8) LDX(c + 1);
        k1_compute<OL>(sW[cur], sX[cur], cq, nq, acc);
        if (c + 1 < 8) {
            if (c + 2 < 8) { CP_WAIT(1); } else { CP_WAIT(0); }  // raw[c+1] (this thread)
            __syncthreads();   // raw[nxt] visible to all; compute done reading bufs
            STX(nxt);
            FOLD(nxt, nxt);
            __syncthreads();   // sW[nxt], sX[nxt] visible for c+1
        }
    }

#undef CPRAW
#undef FOLD
#undef LDX
#undef STX

    // ---- epilogue: norms for all (n,o); cov for focused node ----
    const int foc = focus[g];
#pragma unroll
    for (int cc = 0; cc < 2; cc++) {
        const int col = cq * 2 + cc;
#pragma unroll
        for (int np = 0; np < 2; np++) {
            const int nloc = nq * 4 + np * 2;
            float s0 = 1e-12f, s1 = 1e-12f;
            float lo[OL], hi[OL];
#pragma unroll
            for (int m = 0; m < OL; m++) {
                float l, h;
                upk2(acc[cc][np][m], l, h);
                l *= INV_SQMZ; h *= INV_SQMZ;
                s0 = fmaf(l, l, s0); s1 = fmaf(h, h, s1);
                lo[m] = l; hi[m] = h;
            }
            const int na = n0 + nloc;
            g_sinv[(size_t)na * 384 + L * 128 + col]       = sqrtf(s0);
            g_sinv[(size_t)(na + 1) * 384 + L * 128 + col] = sqrtf(s1);
            if (nloc == foc) {
#pragma unroll
                for (int m = 0; m < OL; m++)
                    g_scov[(size_t)g * 1152 + OFF + col * OL + m] = lo[m];
            }
            if (nloc + 1 == foc) {
#pragma unroll
                for (int m = 0; m < OL; m++)
                    g_scov[(size_t)g * 1152 + OFF + col * OL + m] = hi[m];
            }
        }
    }
}

// ---------------- K2: fused focus + element MLPs ----------------
__global__ void __launch_bounds__(128, 4) k2_mlp(
    const float* __restrict__ gW1f, const float* __restrict__ gb1f,
    const float* __restrict__ gW2f, const float* __restrict__ gb2f,
    const float* __restrict__ gW1e, const float* __restrict__ gb1e,
    const float* __restrict__ gW2e, const float* __restrict__ gb2e)
{
    __shared__ __align__(16) float sS[384 * 32];     // [k][nn]
    const int tid = threadIdx.x;
    const int nb  = blockIdx.x * 32;
    for (int e = tid; e < 96 * 32; e += 128) {
        const int kq = e >> 5, nn = e & 31;
        const int nglob = nb + nn;
        float4 v = make_float4(0.f, 0.f, 0.f, 0.f);
        if (nglob < NN_)
            v = *reinterpret_cast<const float4*>(g_sinv + (size_t)nglob * 384 + kq * 4);
        sS[(kq * 4 + 0) * 32 + nn] = v.x;
        sS[(kq * 4 + 1) * 32 + nn] = v.y;
        sS[(kq * 4 + 2) * 32 + nn] = v.z;
        sS[(kq * 4 + 3) * 32 + nn] = v.w;
    }
    __syncthreads();

    const float bf = gb1f[tid], be = gb1e[tid];
    ull acc2f[16], acc2e[16];
#pragma unroll
    for (int p = 0; p < 16; p++) { acc2f[p] = pk2(bf, bf); acc2e[p] = pk2(be, be); }

    for (int k0 = 0; k0 < 384; k0 += 4) {
        float wf[4], we[4];
#pragma unroll
        for (int q = 0; q < 4; q++) {
            wf[q] = gW1f[(k0 + q) * 128 + tid];
            we[q] = gW1e[(k0 + q) * 128 + tid];
        }
#pragma unroll
        for (int q = 0; q < 4; q++) {
            const ull wf2 = pk2(wf[q], wf[q]);
            const ull we2 = pk2(we[q], we[q]);
            const ulonglong2* x2 = reinterpret_cast<const ulonglong2*>(sS + (k0 + q) * 32);
#pragma unroll
            for (int p8 = 0; p8 < 8; p8++) {
                const ulonglong2 xx = x2[p8];
                fma2_(acc2f[p8 * 2 + 0], wf2, xx.x);
                fma2_(acc2f[p8 * 2 + 1], wf2, xx.y);
                fma2_(acc2e[p8 * 2 + 0], we2, xx.x);
                fma2_(acc2e[p8 * 2 + 1], we2, xx.y);
            }
        }
    }

    float accf[32], acce[32];
#pragma unroll
    for (int p = 0; p < 16; p++) {
        upk2(acc2f[p], accf[2 * p], accf[2 * p + 1]);
        upk2(acc2e[p], acce[2 * p], acce[2 * p + 1]);
    }

    const float w2f = gW2f[tid];
    float w2e[4];
#pragma unroll
    for (int z = 0; z < 4; z++) w2e[z] = gW2e[tid * 4 + z];
    const int lane = tid & 31, wid = tid >> 5;
    __syncthreads();
    float* sR = sS;
    for (int nn = 0; nn < 32; nn++) {
        const float hf = fmaxf(accf[nn], 0.f);
        const float he = fmaxf(acce[nn], 0.f);
        float v0 = hf * w2f, v1 = he * w2e[0], v2 = he * w2e[1],
              v3 = he * w2e[2], v4 = he * w2e[3];
#pragma unroll
        for (int s = 16; s > 0; s >>= 1) {
            v0 += __shfl_down_sync(0xffffffffu, v0, s);
            v1 += __shfl_down_sync(0xffffffffu, v1, s);
            v2 += __shfl_down_sync(0xffffffffu, v2, s);
            v3 += __shfl_down_sync(0xffffffffu, v3, s);
            v4 += __shfl_down_sync(0xffffffffu, v4, s);
        }
        if (lane == 0) {
            const int base = (wid * 32 + nn) * 5;
            sR[base + 0] = v0; sR[base + 1] = v1; sR[base + 2] = v2;
            sR[base + 3] = v3; sR[base + 4] = v4;
        }
    }
    __syncthreads();
    if (tid < 32) {
        const int nglob = nb + tid;
        if (nglob < NN_) {
            float f = gb2f[0];
#pragma unroll
            for (int w = 0; w < 4; w++) f += sR[(w * 32 + tid) * 5 + 0];
            g_fl[nglob] = f;
#pragma unroll
            for (int z = 0; z < 4; z++) {
                float e = gb2e[z];
#pragma unroll
                for (int w = 0; w < 4; w++) e += sR[(w * 32 + tid) * 5 + 1 + z];
                g_el[(size_t)nglob * 4 + z] = e;
            }
        }
    }
}

// ---------------- K3: group softmaxes / entropies ----------------
__global__ void __launch_bounds__(128) k3_group(
    const float* __restrict__ bag, const int* __restrict__ ptr,
    const int* __restrict__ focus, const int* __restrict__ element,
    float* __restrict__ out)
{
    const int g = blockIdx.x * 4 + (threadIdx.x >> 5);
    const int lane = threadIdx.x & 31;
    if (g >= GG_) return;
    const int n0 = ptr[g];
    const int cnt = ptr[g + 1] - n0;
    const int foc = focus[g];
    const int zel = element[g];
    const bool valid = lane < cnt;
    const int n = n0 + lane;
    float f = valid ? g_fl[n] : -3.0e38f;
    float mx = f;
#pragma unroll
    for (int s = 16; s > 0; s >>= 1) mx = fmaxf(mx, __shfl_xor_sync(0xffffffffu, mx, s));
    const float ex = valid ? expf(f - mx) : 0.f;
    const float S  = wsum(ex);
    const float fp = ex / S;
    const float hfocus = wsum(valid ? -fp * logf(fp + 1e-20f) : 0.f);
    float hel = 0.f, pzel = 0.f;
    if (valid) {
        float lz[4];
        float m4 = -3.0e38f;
#pragma unroll
        for (int z = 0; z < 4; z++) {
            float v = g_el[(size_t)n * 4 + z];
            v = (bag[g * 4 + z] > 0.f) ? v : -1e9f;
            lz[z] = v; m4 = fmaxf(m4, v);
        }
        float s4 = 0.f;
#pragma unroll
        for (int z = 0; z < 4; z++) { lz[z] = expf(lz[z] - m4); s4 += lz[z]; }
#pragma unroll
        for (int z = 0; z < 4; z++) {
            lz[z] /= s4;
            hel -= lz[z] * logf(fmaxf(lz[z], 1e-20f));
        }
        pzel = lz[zel];
    }
    const float hef = wsum(fp * hel);
    const float lp = wsum((valid && lane == foc)
                          ? (logf(fp + 1e-20f) + logf(pzel + 1e-20f)) : 0.f);
    if (lane == 0) { g_lp12[g] = lp; out[2 * g + 1] = hfocus + hef; }
}

// ---------------- K5: distance MLP/GMM + cond + orientation logZ ----------------
__global__ void __launch_bounds__(128) k5_final(
    const int* __restrict__ ptr, const int* __restrict__ focus,
    const int* __restrict__ element, const float* __restrict__ distance,
    const float* __restrict__ orientation, const float* __restrict__ W_mix,
    const float* __restrict__ W1d, const float* __restrict__ b1d,
    const float* __restrict__ W2d, const float* __restrict__ b2d,
    const float* __restrict__ d_log_stds, float* __restrict__ out)
{
    const int tid = threadIdx.x, lane = tid & 31, wq = tid >> 5;
    const int gbase = blockIdx.x * 4;
    __shared__ float sSI[4][384];
    __shared__ int   sGI[4], sEl[4];
    __shared__ float sRed[4][4][6];
    if (tid < 4) {
        const int g = gbase + tid;
        sGI[tid] = (g < GG_) ? (ptr[g] + focus[g]) : 0;
        sEl[tid] = (g < GG_) ? element[g] : 0;
    }
    __syncthreads();
#pragma unroll
    for (int q = 0; q < 4; q++)
        for (int k = tid; k < 384; k += 128)
            sSI[q][k] = g_sinv[(size_t)sGI[q] * 384 + k];
    __syncthreads();

    float acc[4];
    const float b1 = b1d[tid];
#pragma unroll
    for (int q = 0; q < 4; q++) acc[q] = b1;
    for (int k = 0; k < 384; k++) {
        const float w = W1d[k * 128 + tid];
#pragma unroll
        for (int q = 0; q < 4; q++) acc[q] = fmaf(w, sSI[q][k], acc[q]);
    }
#pragma unroll
    for (int q = 0; q < 4; q++) acc[q] += W1d[(384 + sEl[q]) * 128 + tid];

    float w2[6];
#pragma unroll
    for (int j = 0; j < 6; j++) w2[j] = W2d[tid * 6 + j];
#pragma unroll
    for (int q = 0; q < 4; q++) {
        const float h = fmaxf(acc[q], 0.f);
        float v[6];
#pragma unroll
        for (int j = 0; j < 6; j++) v[j] = h * w2[j];
#pragma unroll
        for (int s = 16; s > 0; s >>= 1)
#pragma unroll
            for (int j = 0; j < 6; j++) v[j] += __shfl_down_sync(0xffffffffu, v[j], s);
        if (lane == 0)
#pragma unroll
            for (int j = 0; j < 6; j++) sRed[wq][q][j] = v[j];
    }
    __syncthreads();

    const int g = gbase + wq;
    if (g >= GG_) return;
    float hj[6];
#pragma unroll
    for (int j = 0; j < 6; j++)
        hj[j] = sRed[0][wq][j] + sRed[1][wq][j] + sRed[2][wq][j] + sRed[3][wq][j] + b2d[j];

    const float d = distance[g];
    float lm = fmaxf(hj[0], fmaxf(hj[1], hj[2]));
    float se = expf(hj[0] - lm) + expf(hj[1] - lm) + expf(hj[2] - lm);
    const float lse = lm + logf(se);
    float aj[3];
#pragma unroll
    for (int j = 0; j < 3; j++) {
        const float mean = tanhf(hj[3 + j]) * 0.45f + 1.35f;
        const float std  = fmaxf(expf(d_log_stds[j]), 1e-6f);
        const float t = (d - mean) / std;
        aj[j] = (hj[j] - lse) - 0.5f * t * t - logf(std) - 0.91893853320467274f;
    }
    float am = fmaxf(aj[0], fmaxf(aj[1], aj[2]));
    const float lp_dist = am + logf(expf(aj[0] - am) + expf(aj[1] - am) + expf(aj[2] - am));

    float bess[8];
#pragma unroll
    for (int k = 0; k < 8; k++)
        bess[k] = 1.0540925533894598f * sinf((float)(k + 1) * 3.14159265358979f * d / 1.8f) / d;

    const int zel = sEl[wq];
    float cond[9];
#pragma unroll
    for (int j = 0; j < 9; j++) cond[j] = 0.f;
    const float* scov = g_scov + (size_t)g * 1152;
#pragma unroll
    for (int ib = 0; ib < 4; ib++) {
        const int i = lane + ib * 32;
        {
            float tw = 0.f;
#pragma unroll
            for (int k = 0; k < 8; k++)
                tw = fmaf(bess[k], W_mix[k * 1536 + 0 * 512 + i * 4 + zel], tw);
            tw *= 0.3535533905932738f;
            cond[0] = fmaf(scov[i], tw, cond[0]);
        }
        {
            float tw = 0.f;
#pragma unroll
            for (int k = 0; k < 8; k++)
                tw = fmaf(bess[k], W_mix[k * 1536 + 1 * 512 + i * 4 + zel], tw);
            tw *= 0.3535533905932738f;
#pragma unroll
            for (int m = 0; m < 3; m++)
                cond[1 + m] = fmaf(scov[128 + i * 3 + m], tw, cond[1 + m]);
        }
        {
            float tw = 0.f;
#pragma unroll
            for (int k = 0; k < 8; k++)
                tw = fmaf(bess[k], W_mix[k * 1536 + 2 * 512 + i * 4 + zel], tw);
            tw *= 0.3535533905932738f;
#pragma unroll
            for (int m = 0; m < 5; m++)
                cond[4 + m] = fmaf(scov[512 + i * 5 + m], tw, cond[4 + m]);
        }
    }
#pragma unroll
    for (int j = 0; j < 9; j++) cond[j] = wsum(cond[j]) * INV_SQMZ;

    float m_run = -3.0e38f, s_run = 0.f;
    for (int t = 0; t < 128; t++) {
        const int p = lane + 32 * t;
        float f = 0.f;
#pragma unroll
        for (int j = 0; j < 9; j++) f = fmaf(cond[j], g_Y[j * PGRID + p], f);
        f *= 10.0f;
        const float nm = fmaxf(m_run, f);
        s_run = s_run * __expf(m_run - nm) + __expf(f - nm);
        m_run = nm;
    }
#pragma unroll
    for (int s = 16; s > 0; s >>= 1) {
        const float om = __shfl_xor_sync(0xffffffffu, m_run, s);
        const float os = __shfl_xor_sync(0xffffffffu, s_run, s);
        const float nm = fmaxf(m_run, om);
        s_run = s_run * __expf(m_run - nm) + os * __expf(om - nm);
        m_run = nm;
    }
    const float logZ = m_run + logf(s_run) - 8.317766166719343f + 2.5310242469692907f;

    if (lane == 0) {
        float ox = orientation[g * 3 + 0], oy = orientation[g * 3 + 1],
              oz = orientation[g * 3 + 2];
        const float inv = rsqrtf(ox * ox + oy * oy + oz * oz);
        ox *= inv; oy *= inv; oz *= inv;
        float sh[9];
        sh[0] = 0.28209479177387814f;
        sh[1] = 0.4886025119029199f * oy;
        sh[2] = 0.4886025119029199f * oz;
        sh[3] = 0.4886025119029199f * ox;
        sh[4] = 1.0925484305920792f * ox * oy;
        sh[5] = 1.0925484305920792f * oy * oz;
        sh[6] = 0.31539156525252005f * (3.f * oz * oz - 1.f);
        sh[7] = 1.0925484305920792f * ox * oz;
        sh[8] = 0.5462742152960396f * (ox * ox - oy * oy);
        float f_x = 0.f;
#pragma unroll
        for (int j = 0; j < 9; j++) f_x = fmaf(cond[j], sh[j], f_x);
        const float lp_ori = 10.0f * f_x - logZ;
        out[2 * g] = g_lp12[g] + lp_dist + lp_ori;
    }
}

// ---------------- launch ----------------
extern "C" void kernel_launch(void* const* d_in, const int* in_sizes, int n_in,
                              void* d_out, int out_size) {
    const float* s_inter     = (const float*)d_in[0];
    const float* bag         = (const float*)d_in[1];
    const int*   ptr         = (const int*)  d_in[3];
    const int*   focus       = (const int*)  d_in[4];
    const int*   element     = (const int*)  d_in[5];
    const float* distance    = (const float*)d_in[6];
    const float* orientation = (const float*)d_in[7];
    const float* W_bag       = (const float*)d_in[8];
    const float* d_log_stds  = (const float*)d_in[9];
    const float* W_mix       = (const float*)d_in[10];
    const float* W1f = (const float*)d_in[11];
    const float* b1f = (const float*)d_in[12];
    const float* W2f = (const float*)d_in[13];
    const float* b2f = (const float*)d_in[14];
    const float* W1e = (const float*)d_in[15];
    const float* b1e = (const float*)d_in[16];
    const float* W2e = (const float*)d_in[17];
    const float* b2e = (const float*)d_in[18];
    const float* W1d = (const float*)d_in[19];
    const float* b1d = (const float*)d_in[20];
    const float* W2d = (const float*)d_in[21];
    const float* b2d = (const float*)d_in[22];
    float* out = (float*)d_out;

    k0_ygrid<<<32, 128>>>();
    k1_cov<2><<<GG_, 320>>>(s_inter, bag, ptr, focus, W_bag);
    k1_cov<1><<<GG_, 320>>>(s_inter, bag, ptr, focus, W_bag);
    k1_cov<0><<<GG_, 320>>>(s_inter, bag, ptr, focus, W_bag);
    k2_mlp<<<(NN_ + 31) / 32, 128>>>(W1f, b1f, W2f, b2f, W1e, b1e, W2e, b2e);
    k3_group<<<(GG_ + 3) / 4, 128>>>(bag, ptr, focus, element, out);
    k5_final<<<(GG_ + 3) / 4, 128>>>(ptr, focus, element, distance, orientation,
                                     W_mix, W1d, b1d, W2d, b2d, d_log_stds, out);
}

// round 15
// speedup vs baseline: 1.1236x; 1.1236x over previous
#include <cuda_runtime.h>
#include <cuda_bf16.h>
#include <math.h>
#include <stdint.h>

#define NN_ 50000
#define GG_ 2500
#define PGRID 4096
#define INV_SQMZ 0.04419417382415922f

typedef unsigned long long ull;

// ---------------- device scratch ----------------
__device__ float g_sinv[(size_t)NN_ * 384];   // per-node invariant norms
__device__ float g_scov[(size_t)GG_ * 1152];  // focused-node cov vectors (with /SQ_MZ)
__device__ float g_fl[NN_];                   // focus logits
__device__ float g_el[(size_t)NN_ * 4];       // element logits
__device__ float g_Y[9 * PGRID];              // SH basis on Fibonacci grid, [j][p]
__device__ float g_lp12[GG_];                 // lp_focus + lp_element

__device__ __forceinline__ float wsum(float v) {
#pragma unroll
    for (int s = 16; s > 0; s >>= 1) v += __shfl_xor_sync(0xffffffffu, v, s);
    return v;
}

__device__ __forceinline__ ull pk2(float lo, float hi) {
    ull r;
    asm("mov.b64 %0, {%1, %2};" : "=l"(r) : "f"(lo), "f"(hi));
    return r;
}
__device__ __forceinline__ void upk2(ull v, float& lo, float& hi) {
    asm("mov.b64 {%0, %1}, %2;" : "=f"(lo), "=f"(hi) : "l"(v));
}
__device__ __forceinline__ void fma2_(ull& d, ull a, ull b) {
    asm("fma.rn.f32x2 %0, %1, %2, %0;" : "+l"(d) : "l"(a), "l"(b));
}

// ---------------- K0: build Y_GRID ----------------
__global__ void k0_ygrid() {
    int i = blockIdx.x * blockDim.x + threadIdx.x;
    if (i >= PGRID) return;
    double ph = 3.14159265358979323846 * (3.0 - sqrt(5.0)) * (double)i;
    double z  = 1.0 - 2.0 * ((double)i + 0.5) / (double)PGRID;
    double rr = 1.0 - z * z; if (rr < 0.0) rr = 0.0;
    double r  = sqrt(rr);
    float x  = (float)(r * cos(ph));
    float y  = (float)(r * sin(ph));
    float zf = (float)z;
    g_Y[0 * PGRID + i] = 0.28209479177387814f;
    g_Y[1 * PGRID + i] = 0.4886025119029199f * y;
    g_Y[2 * PGRID + i] = 0.4886025119029199f * zf;
    g_Y[3 * PGRID + i] = 0.4886025119029199f * x;
    g_Y[4 * PGRID + i] = 1.0925484305920792f * x * y;
    g_Y[5 * PGRID + i] = 1.0925484305920792f * y * zf;
    g_Y[6 * PGRID + i] = 0.31539156525252005f * (3.f * zf * zf - 1.f);
    g_Y[7 * PGRID + i] = 1.0925484305920792f * x * zf;
    g_Y[8 * PGRID + i] = 0.5462742152960396f * (x * x - y * y);
}

// ---------------- K1: per-group cov GEMM with SMEM-resident folded W ----------------
// 320 threads: cq = tid&63 -> cols {2cq, 2cq+1}; nq = tid>>6 -> nodes 4nq..4nq+3.
// Fold W_eff = sum_z bag[z]*W_bag[l,:,z,:] ONCE into 64KB SMEM (from L2-resident
// W_bag), then the 128-k mainloop streams only the tiny X tiles (double-buffered).
template <int OL>
__device__ __forceinline__ void k1_compute(
    const float* __restrict__ sWb, const float* __restrict__ sXb,
    int cq, int nq, ull (&acc)[2][2][OL])
{
    const float* wp = sWb + cq * 2;
    const float* xp = sXb + nq * 4;
#pragma unroll 8
    for (int kk = 0; kk < 16; kk++) {
        const float2 w = *reinterpret_cast<const float2*>(wp + kk * 128);
        const ull wd0 = pk2(w.x, w.x);
        const ull wd1 = pk2(w.y, w.y);
#pragma unroll
        for (int m = 0; m < OL; m++) {
            const ulonglong2 xv = *reinterpret_cast<const ulonglong2*>(
                xp + (kk * OL + m) * 20);
            fma2_(acc[0][0][m], wd0, xv.x);
            fma2_(acc[0][1][m], wd0, xv.y);
            fma2_(acc[1][0][m], wd1, xv.x);
            fma2_(acc[1][1][m], wd1, xv.y);
        }
    }
}

template <int L>
__global__ void __launch_bounds__(320, (L == 2) ? 2 : 3) k1_cov(
    const float* __restrict__ s_inter, const float* __restrict__ bag,
    const int* __restrict__ ptr, const int* __restrict__ focus,
    const float* __restrict__ W_bag)
{
    constexpr int OL  = (L == 0) ? 1 : (L == 1 ? 3 : 5);
    constexpr int OFF = (L == 0) ? 0 : (L == 1 ? 128 : 512);
    constexpr int XCH = 16 * OL;    // floats per node per chunk
    constexpr int NPT = OL;         // X elements per thread per chunk (exact)
    constexpr int XSZ = OL * 16 * 20;

    extern __shared__ __align__(16) float smem[];
    float* sW  = smem;              // [128][128] folded weights, 64KB
    float* sXa = smem + 16384;      // X double buffer
    float* sXb = sXa + XSZ;

    const int g   = blockIdx.x;
    const int tid = threadIdx.x;
    const int cq  = tid & 63;
    const int nq  = tid >> 6;
    const int n0  = ptr[g];
    const float b0 = bag[g * 4 + 0], b1 = bag[g * 4 + 1];
    const float b2 = bag[g * 4 + 2], b3 = bag[g * 4 + 3];
    const float* Wraw = W_bag + (size_t)L * 65536;
    const float* Xg   = s_inter + (size_t)n0 * 1152 + OFF;

    ull acc[2][2][OL];
#pragma unroll
    for (int cc = 0; cc < 2; cc++)
#pragma unroll
        for (int np = 0; np < 2; np++)
#pragma unroll
            for (int m = 0; m < OL; m++) acc[cc][np][m] = 0ull;

    // ---- fold the ENTIRE W_eff into SMEM once (W_bag is L2-resident) ----
#pragma unroll 2
    for (int t = tid; t < 4096; t += 320) {
        const int ii = t >> 5, o4 = (t & 31) << 2;
        const float* wp = Wraw + (size_t)ii * 512 + o4;
        const float4 w0 = *reinterpret_cast<const float4*>(wp);
        const float4 w1 = *reinterpret_cast<const float4*>(wp + 128);
        const float4 w2 = *reinterpret_cast<const float4*>(wp + 256);
        const float4 w3 = *reinterpret_cast<const float4*>(wp + 384);
        float4 r;
        r.x = fmaf(b0, w0.x, fmaf(b1, w1.x, fmaf(b2, w2.x, b3 * w3.x)));
        r.y = fmaf(b0, w0.y, fmaf(b1, w1.y, fmaf(b2, w2.y, b3 * w3.y)));
        r.z = fmaf(b0, w0.z, fmaf(b1, w1.z, fmaf(b2, w2.z, b3 * w3.z)));
        r.w = fmaf(b0, w0.w, fmaf(b1, w1.w, fmaf(b2, w2.w, b3 * w3.w)));
        *reinterpret_cast<float4*>(sW + ii * 128 + o4) = r;
    }

    float xr[NPT];

    // ---- X chunk -> regs ----
#define LDX(C)                                                              \
    {                                                                       \
        const float* src = Xg + (C) * XCH;                                  \
        _Pragma("unroll")                                                   \
        for (int t = 0; t < NPT; t++) {                                     \
            const int idx = tid + t * 320;                                  \
            const int nl = idx / XCH;                                       \
            const int j  = idx - nl * XCH;                                  \
            xr[t] = src[(size_t)nl * 1152 + j];                             \
        }                                                                   \
    }
    // ---- X regs -> smem (transposed) ----
#define STX(B)                                                              \
    {                                                                       \
        _Pragma("unroll")                                                   \
        for (int t = 0; t < NPT; t++) {                                     \
            const int idx = tid + t * 320;                                  \
            const int nl = idx / XCH;                                       \
            const int j  = idx - nl * XCH;                                  \
            (B)[j * 20 + nl] = xr[t];                                       \
        }                                                                   \
    }

    LDX(0);
    STX(sXa);             // disjoint from sW; own region, visible after barrier
    __syncthreads();      // sW + sXa visible to all

    // ---- main loop, 8 chunks of 16 k ----
#pragma unroll
    for (int c = 0; c < 8; c++) {
        const float* sXcur = (c & 1) ? sXb : sXa;
        float* sXnxt = (c & 1) ? sXa : sXb;
        if (c + 1 < 8) LDX(c + 1);
        k1_compute<OL>(sW + c * 16 * 128, sXcur, cq, nq, acc);
        if (c + 1 < 8) {
            __syncthreads();   // all done reading sXnxt (from compute c-1)
            STX(sXnxt);
            __syncthreads();   // sXnxt visible for chunk c+1
        }
    }

#undef LDX
#undef STX

    // ---- epilogue: norms for all (n,o); cov for focused node ----
    const int foc = focus[g];
#pragma unroll
    for (int cc = 0; cc < 2; cc++) {
        const int col = cq * 2 + cc;
#pragma unroll
        for (int np = 0; np < 2; np++) {
            const int nloc = nq * 4 + np * 2;
            float s0 = 1e-12f, s1 = 1e-12f;
            float lo[OL], hi[OL];
#pragma unroll
            for (int m = 0; m < OL; m++) {
                float l, h;
                upk2(acc[cc][np][m], l, h);
                l *= INV_SQMZ; h *= INV_SQMZ;
                s0 = fmaf(l, l, s0); s1 = fmaf(h, h, s1);
                lo[m] = l; hi[m] = h;
            }
            const int na = n0 + nloc;
            g_sinv[(size_t)na * 384 + L * 128 + col]       = sqrtf(s0);
            g_sinv[(size_t)(na + 1) * 384 + L * 128 + col] = sqrtf(s1);
            if (nloc == foc) {
#pragma unroll
                for (int m = 0; m < OL; m++)
                    g_scov[(size_t)g * 1152 + OFF + col * OL + m] = lo[m];
            }
            if (nloc + 1 == foc) {
#pragma unroll
                for (int m = 0; m < OL; m++)
                    g_scov[(size_t)g * 1152 + OFF + col * OL + m] = hi[m];
            }
        }
    }
}

// ---------------- K2: fused focus + element MLPs ----------------
__global__ void __launch_bounds__(128, 4) k2_mlp(
    const float* __restrict__ gW1f, const float* __restrict__ gb1f,
    const float* __restrict__ gW2f, const float* __restrict__ gb2f,
    const float* __restrict__ gW1e, const float* __restrict__ gb1e,
    const float* __restrict__ gW2e, const float* __restrict__ gb2e)
{
    __shared__ __align__(16) float sS[384 * 32];     // [k][nn]
    const int tid = threadIdx.x;
    const int nb  = blockIdx.x * 32;
    for (int e = tid; e < 96 * 32; e += 128) {
        const int kq = e >> 5, nn = e & 31;
        const int nglob = nb + nn;
        float4 v = make_float4(0.f, 0.f, 0.f, 0.f);
        if (nglob < NN_)
            v = *reinterpret_cast<const float4*>(g_sinv + (size_t)nglob * 384 + kq * 4);
        sS[(kq * 4 + 0) * 32 + nn] = v.x;
        sS[(kq * 4 + 1) * 32 + nn] = v.y;
        sS[(kq * 4 + 2) * 32 + nn] = v.z;
        sS[(kq * 4 + 3) * 32 + nn] = v.w;
    }
    __syncthreads();

    const float bf = gb1f[tid], be = gb1e[tid];
    ull acc2f[16], acc2e[16];
#pragma unroll
    for (int p = 0; p < 16; p++) { acc2f[p] = pk2(bf, bf); acc2e[p] = pk2(be, be); }

    for (int k0 = 0; k0 < 384; k0 += 4) {
        float wf[4], we[4];
#pragma unroll
        for (int q = 0; q < 4; q++) {
            wf[q] = gW1f[(k0 + q) * 128 + tid];
            we[q] = gW1e[(k0 + q) * 128 + tid];
        }
#pragma unroll
        for (int q = 0; q < 4; q++) {
            const ull wf2 = pk2(wf[q], wf[q]);
            const ull we2 = pk2(we[q], we[q]);
            const ulonglong2* x2 = reinterpret_cast<const ulonglong2*>(sS + (k0 + q) * 32);
#pragma unroll
            for (int p8 = 0; p8 < 8; p8++) {
                const ulonglong2 xx = x2[p8];
                fma2_(acc2f[p8 * 2 + 0], wf2, xx.x);
                fma2_(acc2f[p8 * 2 + 1], wf2, xx.y);
                fma2_(acc2e[p8 * 2 + 0], we2, xx.x);
                fma2_(acc2e[p8 * 2 + 1], we2, xx.y);
            }
        }
    }

    float accf[32], acce[32];
#pragma unroll
    for (int p = 0; p < 16; p++) {
        upk2(acc2f[p], accf[2 * p], accf[2 * p + 1]);
        upk2(acc2e[p], acce[2 * p], acce[2 * p + 1]);
    }

    const float w2f = gW2f[tid];
    float w2e[4];
#pragma unroll
    for (int z = 0; z < 4; z++) w2e[z] = gW2e[tid * 4 + z];
    const int lane = tid & 31, wid = tid >> 5;
    __syncthreads();
    float* sR = sS;
    for (int nn = 0; nn < 32; nn++) {
        const float hf = fmaxf(accf[nn], 0.f);
        const float he = fmaxf(acce[nn], 0.f);
        float v0 = hf * w2f, v1 = he * w2e[0], v2 = he * w2e[1],
              v3 = he * w2e[2], v4 = he * w2e[3];
#pragma unroll
        for (int s = 16; s > 0; s >>= 1) {
            v0 += __shfl_down_sync(0xffffffffu, v0, s);
            v1 += __shfl_down_sync(0xffffffffu, v1, s);
            v2 += __shfl_down_sync(0xffffffffu, v2, s);
            v3 += __shfl_down_sync(0xffffffffu, v3, s);
            v4 += __shfl_down_sync(0xffffffffu, v4, s);
        }
        if (lane == 0) {
            const int base = (wid * 32 + nn) * 5;
            sR[base + 0] = v0; sR[base + 1] = v1; sR[base + 2] = v2;
            sR[base + 3] = v3; sR[base + 4] = v4;
        }
    }
    __syncthreads();
    if (tid < 32) {
        const int nglob = nb + tid;
        if (nglob < NN_) {
            float f = gb2f[0];
#pragma unroll
            for (int w = 0; w < 4; w++) f += sR[(w * 32 + tid) * 5 + 0];
            g_fl[nglob] = f;
#pragma unroll
            for (int z = 0; z < 4; z++) {
                float e = gb2e[z];
#pragma unroll
                for (int w = 0; w < 4; w++) e += sR[(w * 32 + tid) * 5 + 1 + z];
                g_el[(size_t)nglob * 4 + z] = e;
            }
        }
    }
}

// ---------------- K3: group softmaxes / entropies ----------------
__global__ void __launch_bounds__(128) k3_group(
    const float* __restrict__ bag, const int* __restrict__ ptr,
    const int* __restrict__ focus, const int* __restrict__ element,
    float* __restrict__ out)
{
    const int g = blockIdx.x * 4 + (threadIdx.x >> 5);
    const int lane = threadIdx.x & 31;
    if (g >= GG_) return;
    const int n0 = ptr[g];
    const int cnt = ptr[g + 1] - n0;
    const int foc = focus[g];
    const int zel = element[g];
    const bool valid = lane < cnt;
    const int n = n0 + lane;
    float f = valid ? g_fl[n] : -3.0e38f;
    float mx = f;
#pragma unroll
    for (int s = 16; s > 0; s >>= 1) mx = fmaxf(mx, __shfl_xor_sync(0xffffffffu, mx, s));
    const float ex = valid ? expf(f - mx) : 0.f;
    const float S  = wsum(ex);
    const float fp = ex / S;
    const float hfocus = wsum(valid ? -fp * logf(fp + 1e-20f) : 0.f);
    float hel = 0.f, pzel = 0.f;
    if (valid) {
        float lz[4];
        float m4 = -3.0e38f;
#pragma unroll
        for (int z = 0; z < 4; z++) {
            float v = g_el[(size_t)n * 4 + z];
            v = (bag[g * 4 + z] > 0.f) ? v : -1e9f;
            lz[z] = v; m4 = fmaxf(m4, v);
        }
        float s4 = 0.f;
#pragma unroll
        for (int z = 0; z < 4; z++) { lz[z] = expf(lz[z] - m4); s4 += lz[z]; }
#pragma unroll
        for (int z = 0; z < 4; z++) {
            lz[z] /= s4;
            hel -= lz[z] * logf(fmaxf(lz[z], 1e-20f));
        }
        pzel = lz[zel];
    }
    const float hef = wsum(fp * hel);
    const float lp = wsum((valid && lane == foc)
                          ? (logf(fp + 1e-20f) + logf(pzel + 1e-20f)) : 0.f);
    if (lane == 0) { g_lp12[g] = lp; out[2 * g + 1] = hfocus + hef; }
}

// ---------------- K5: distance MLP/GMM + cond + orientation logZ ----------------
__global__ void __launch_bounds__(128) k5_final(
    const int* __restrict__ ptr, const int* __restrict__ focus,
    const int* __restrict__ element, const float* __restrict__ distance,
    const float* __restrict__ orientation, const float* __restrict__ W_mix,
    const float* __restrict__ W1d, const float* __restrict__ b1d,
    const float* __restrict__ W2d, const float* __restrict__ b2d,
    const float* __restrict__ d_log_stds, float* __restrict__ out)
{
    const int tid = threadIdx.x, lane = tid & 31, wq = tid >> 5;
    const int gbase = blockIdx.x * 4;
    __shared__ float sSI[4][384];
    __shared__ int   sGI[4], sEl[4];
    __shared__ float sRed[4][4][6];
    if (tid < 4) {
        const int g = gbase + tid;
        sGI[tid] = (g < GG_) ? (ptr[g] + focus[g]) : 0;
        sEl[tid] = (g < GG_) ? element[g] : 0;
    }
    __syncthreads();
#pragma unroll
    for (int q = 0; q < 4; q++)
        for (int k = tid; k < 384; k += 128)
            sSI[q][k] = g_sinv[(size_t)sGI[q] * 384 + k];
    __syncthreads();

    float acc[4];
    const float b1 = b1d[tid];
#pragma unroll
    for (int q = 0; q < 4; q++) acc[q] = b1;
    for (int k = 0; k < 384; k++) {
        const float w = W1d[k * 128 + tid];
#pragma unroll
        for (int q = 0; q < 4; q++) acc[q] = fmaf(w, sSI[q][k], acc[q]);
    }
#pragma unroll
    for (int q = 0; q < 4; q++) acc[q] += W1d[(384 + sEl[q]) * 128 + tid];

    float w2[6];
#pragma unroll
    for (int j = 0; j < 6; j++) w2[j] = W2d[tid * 6 + j];
#pragma unroll
    for (int q = 0; q < 4; q++) {
        const float h = fmaxf(acc[q], 0.f);
        float v[6];
#pragma unroll
        for (int j = 0; j < 6; j++) v[j] = h * w2[j];
#pragma unroll
        for (int s = 16; s > 0; s >>= 1)
#pragma unroll
            for (int j = 0; j < 6; j++) v[j] += __shfl_down_sync(0xffffffffu, v[j], s);
        if (lane == 0)
#pragma unroll
            for (int j = 0; j < 6; j++) sRed[wq][q][j] = v[j];
    }
    __syncthreads();

    const int g = gbase + wq;
    if (g >= GG_) return;
    float hj[6];
#pragma unroll
    for (int j = 0; j < 6; j++)
        hj[j] = sRed[0][wq][j] + sRed[1][wq][j] + sRed[2][wq][j] + sRed[3][wq][j] + b2d[j];

    const float d = distance[g];
    float lm = fmaxf(hj[0], fmaxf(hj[1], hj[2]));
    float se = expf(hj[0] - lm) + expf(hj[1] - lm) + expf(hj[2] - lm);
    const float lse = lm + logf(se);
    float aj[3];
#pragma unroll
    for (int j = 0; j < 3; j++) {
        const float mean = tanhf(hj[3 + j]) * 0.45f + 1.35f;
        const float std  = fmaxf(expf(d_log_stds[j]), 1e-6f);
        const float t = (d - mean) / std;
        aj[j] = (hj[j] - lse) - 0.5f * t * t - logf(std) - 0.91893853320467274f;
    }
    float am = fmaxf(aj[0], fmaxf(aj[1], aj[2]));
    const float lp_dist = am + logf(expf(aj[0] - am) + expf(aj[1] - am) + expf(aj[2] - am));

    float bess[8];
#pragma unroll
    for (int k = 0; k < 8; k++)
        bess[k] = 1.0540925533894598f * sinf((float)(k + 1) * 3.14159265358979f * d / 1.8f) / d;

    const int zel = sEl[wq];
    float cond[9];
#pragma unroll
    for (int j = 0; j < 9; j++) cond[j] = 0.f;
    const float* scov = g_scov + (size_t)g * 1152;
#pragma unroll
    for (int ib = 0; ib < 4; ib++) {
        const int i = lane + ib * 32;
        {
            float tw = 0.f;
#pragma unroll
            for (int k = 0; k < 8; k++)
                tw = fmaf(bess[k], W_mix[k * 1536 + 0 * 512 + i * 4 + zel], tw);
            tw *= 0.3535533905932738f;
            cond[0] = fmaf(scov[i], tw, cond[0]);
        }
        {
            float tw = 0.f;
#pragma unroll
            for (int k = 0; k < 8; k++)
                tw = fmaf(bess[k], W_mix[k * 1536 + 1 * 512 + i * 4 + zel], tw);
            tw *= 0.3535533905932738f;
#pragma unroll
            for (int m = 0; m < 3; m++)
                cond[1 + m] = fmaf(scov[128 + i * 3 + m], tw, cond[1 + m]);
        }
        {
            float tw = 0.f;
#pragma unroll
            for (int k = 0; k < 8; k++)
                tw = fmaf(bess[k], W_mix[k * 1536 + 2 * 512 + i * 4 + zel], tw);
            tw *= 0.3535533905932738f;
#pragma unroll
            for (int m = 0; m < 5; m++)
                cond[4 + m] = fmaf(scov[512 + i * 5 + m], tw, cond[4 + m]);
        }
    }
#pragma unroll
    for (int j = 0; j < 9; j++) cond[j] = wsum(cond[j]) * INV_SQMZ;

    float m_run = -3.0e38f, s_run = 0.f;
    for (int t = 0; t < 128; t++) {
        const int p = lane + 32 * t;
        float f = 0.f;
#pragma unroll
        for (int j = 0; j < 9; j++) f = fmaf(cond[j], g_Y[j * PGRID + p], f);
        f *= 10.0f;
        const float nm = fmaxf(m_run, f);
        s_run = s_run * __expf(m_run - nm) + __expf(f - nm);
        m_run = nm;
    }
#pragma unroll
    for (int s = 16; s > 0; s >>= 1) {
        const float om = __shfl_xor_sync(0xffffffffu, m_run, s);
        const float os = __shfl_xor_sync(0xffffffffu, s_run, s);
        const float nm = fmaxf(m_run, om);
        s_run = s_run * __expf(m_run - nm) + os * __expf(om - nm);
        m_run = nm;
    }
    const float logZ = m_run + logf(s_run) - 8.317766166719343f + 2.5310242469692907f;

    if (lane == 0) {
        float ox = orientation[g * 3 + 0], oy = orientation[g * 3 + 1],
              oz = orientation[g * 3 + 2];
        const float inv = rsqrtf(ox * ox + oy * oy + oz * oz);
        ox *= inv; oy *= inv; oz *= inv;
        float sh[9];
        sh[0] = 0.28209479177387814f;
        sh[1] = 0.4886025119029199f * oy;
        sh[2] = 0.4886025119029199f * oz;
        sh[3] = 0.4886025119029199f * ox;
        sh[4] = 1.0925484305920792f * ox * oy;
        sh[5] = 1.0925484305920792f * oy * oz;
        sh[6] = 0.31539156525252005f * (3.f * oz * oz - 1.f);
        sh[7] = 1.0925484305920792f * ox * oz;
        sh[8] = 0.5462742152960396f * (ox * ox - oy * oy);
        float f_x = 0.f;
#pragma unroll
        for (int j = 0; j < 9; j++) f_x = fmaf(cond[j], sh[j], f_x);
        const float lp_ori = 10.0f * f_x - logZ;
        out[2 * g] = g_lp12[g] + lp_dist + lp_ori;
    }
}

// ---------------- launch ----------------
extern "C" void kernel_launch(void* const* d_in, const int* in_sizes, int n_in,
                              void* d_out, int out_size) {
    const float* s_inter     = (const float*)d_in[0];
    const float* bag         = (const float*)d_in[1];
    const int*   ptr         = (const int*)  d_in[3];
    const int*   focus       = (const int*)  d_in[4];
    const int*   element     = (const int*)  d_in[5];
    const float* distance    = (const float*)d_in[6];
    const float* orientation = (const float*)d_in[7];
    const float* W_bag       = (const float*)d_in[8];
    const float* d_log_stds  = (const float*)d_in[9];
    const float* W_mix       = (const float*)d_in[10];
    const float* W1f = (const float*)d_in[11];
    const float* b1f = (const float*)d_in[12];
    const float* W2f = (const float*)d_in[13];
    const float* b2f = (const float*)d_in[14];
    const float* W1e = (const float*)d_in[15];
    const float* b1e = (const float*)d_in[16];
    const float* W2e = (const float*)d_in[17];
    const float* b2e = (const float*)d_in[18];
    const float* W1d = (const float*)d_in[19];
    const float* b1d = (const float*)d_in[20];
    const float* W2d = (const float*)d_in[21];
    const float* b2d = (const float*)d_in[22];
    float* out = (float*)d_out;

    const int smem2 = 65536 + 2 * 5 * 16 * 20 * 4;  // 78336
    const int smem1 = 65536 + 2 * 3 * 16 * 20 * 4;  // 73216
    const int smem0 = 65536 + 2 * 1 * 16 * 20 * 4;  // 68096
    cudaFuncSetAttribute(k1_cov<2>, cudaFuncAttributeMaxDynamicSharedMemorySize, smem2);
    cudaFuncSetAttribute(k1_cov<1>, cudaFuncAttributeMaxDynamicSharedMemorySize, smem1);
    cudaFuncSetAttribute(k1_cov<0>, cudaFuncAttributeMaxDynamicSharedMemorySize, smem0);

    k0_ygrid<<<32, 128>>>();
    k1_cov<2><<<GG_, 320, smem2>>>(s_inter, bag, ptr, focus, W_bag);
    k1_cov<1><<<GG_, 320, smem1>>>(s_inter, bag, ptr, focus, W_bag);
    k1_cov<0><<<GG_, 320, smem0>>>(s_inter, bag, ptr, focus, W_bag);
    k2_mlp<<<(NN_ + 31) / 32, 128>>>(W1f, b1f, W2f, b2f, W1e, b1e, W2e, b2e);
    k3_group<<<(GG_ + 3) / 4, 128>>>(bag, ptr, focus, element, out);
    k5_final<<<(GG_ + 3) / 4, 128>>>(ptr, focus, element, distance, orientation,
                                     W_mix, W1d, b1d, W2d, b2d, d_log_stds, out);
}

// round 16
// speedup vs baseline: 1.1509x; 1.0243x over previous
#include <cuda_runtime.h>
#include <cuda_bf16.h>
#include <math.h>
#include <stdint.h>

#define NN_ 50000
#define GG_ 2500
#define PGRID 4096
#define INV_SQMZ 0.04419417382415922f

typedef unsigned long long ull;

// ---------------- device scratch ----------------
__device__ float g_sinv[(size_t)NN_ * 384];   // per-node invariant norms
__device__ float g_scov[(size_t)GG_ * 1152];  // focused-node cov vectors (with /SQ_MZ)
__device__ float g_fl[NN_];                   // focus logits
__device__ float g_el[(size_t)NN_ * 4];       // element logits
__device__ float g_Y[9 * PGRID];              // SH basis on Fibonacci grid, [j][p]
__device__ float g_lp12[GG_];                 // lp_focus + lp_element
__device__ float g_wmixT[4 * 3 * 128 * 8];    // W_mix transposed: [zel][l][i][k]

__device__ __forceinline__ float wsum(float v) {
#pragma unroll
    for (int s = 16; s > 0; s >>= 1) v += __shfl_xor_sync(0xffffffffu, v, s);
    return v;
}

__device__ __forceinline__ ull pk2(float lo, float hi) {
    ull r;
    asm("mov.b64 %0, {%1, %2};" : "=l"(r) : "f"(lo), "f"(hi));
    return r;
}
__device__ __forceinline__ void upk2(ull v, float& lo, float& hi) {
    asm("mov.b64 {%0, %1}, %2;" : "=f"(lo), "=f"(hi) : "l"(v));
}
__device__ __forceinline__ void fma2_(ull& d, ull a, ull b) {
    asm("fma.rn.f32x2 %0, %1, %2, %0;" : "+l"(d) : "l"(a), "l"(b));
}

// ---------------- K0: build Y_GRID ----------------
__global__ void k0_ygrid() {
    int i = blockIdx.x * blockDim.x + threadIdx.x;
    if (i >= PGRID) return;
    double ph = 3.14159265358979323846 * (3.0 - sqrt(5.0)) * (double)i;
    double z  = 1.0 - 2.0 * ((double)i + 0.5) / (double)PGRID;
    double rr = 1.0 - z * z; if (rr < 0.0) rr = 0.0;
    double r  = sqrt(rr);
    float x  = (float)(r * cos(ph));
    float y  = (float)(r * sin(ph));
    float zf = (float)z;
    g_Y[0 * PGRID + i] = 0.28209479177387814f;
    g_Y[1 * PGRID + i] = 0.4886025119029199f * y;
    g_Y[2 * PGRID + i] = 0.4886025119029199f * zf;
    g_Y[3 * PGRID + i] = 0.4886025119029199f * x;
    g_Y[4 * PGRID + i] = 1.0925484305920792f * x * y;
    g_Y[5 * PGRID + i] = 1.0925484305920792f * y * zf;
    g_Y[6 * PGRID + i] = 0.31539156525252005f * (3.f * zf * zf - 1.f);
    g_Y[7 * PGRID + i] = 1.0925484305920792f * x * zf;
    g_Y[8 * PGRID + i] = 0.5462742152960396f * (x * x - y * y);
}

// ---------------- kt: transpose W_mix -> [zel][l][i][k] ----------------
__global__ void kt_wmix(const float* __restrict__ W_mix) {
    int e = blockIdx.x * blockDim.x + threadIdx.x;   // 12288 total
    if (e >= 4 * 3 * 128 * 8) return;
    const int k   = e & 7;
    const int i   = (e >> 3) & 127;
    const int l   = (e >> 10) % 3;
    const int zel = e / (3 * 128 * 8);
    g_wmixT[e] = W_mix[k * 1536 + l * 512 + i * 4 + zel];
}

// ---------------- K1: per-group cov GEMM, SMEM-resident folded W ----------------
// 320 threads: cq = tid&63 -> cols {2cq, 2cq+1}; nq = tid>>6 -> nodes 4nq..4nq+3.
// W folded once into 64KB SMEM; X double-buffered with 2-chunk-deep register
// prefetch; ONE barrier per chunk (STX target disjoint from compute source).
template <int OL>
__device__ __forceinline__ void k1_compute(
    const float* __restrict__ sWb, const float* __restrict__ sXb,
    int cq, int nq, ull (&acc)[2][2][OL])
{
    const float* wp = sWb + cq * 2;
    const float* xp = sXb + nq * 4;
#pragma unroll 8
    for (int kk = 0; kk < 16; kk++) {
        const float2 w = *reinterpret_cast<const float2*>(wp + kk * 128);
        const ull wd0 = pk2(w.x, w.x);
        const ull wd1 = pk2(w.y, w.y);
#pragma unroll
        for (int m = 0; m < OL; m++) {
            const ulonglong2 xv = *reinterpret_cast<const ulonglong2*>(
                xp + (kk * OL + m) * 20);
            fma2_(acc[0][0][m], wd0, xv.x);
            fma2_(acc[0][1][m], wd0, xv.y);
            fma2_(acc[1][0][m], wd1, xv.x);
            fma2_(acc[1][1][m], wd1, xv.y);
        }
    }
}

template <int L>
__global__ void __launch_bounds__(320, (L == 2) ? 2 : 3) k1_cov(
    const float* __restrict__ s_inter, const float* __restrict__ bag,
    const int* __restrict__ ptr, const int* __restrict__ focus,
    const float* __restrict__ W_bag)
{
    constexpr int OL  = (L == 0) ? 1 : (L == 1 ? 3 : 5);
    constexpr int OFF = (L == 0) ? 0 : (L == 1 ? 128 : 512);
    constexpr int XCH = 16 * OL;    // floats per node per chunk
    constexpr int NPT = OL;         // X elements per thread per chunk (exact)
    constexpr int XSZ = OL * 16 * 20;

    extern __shared__ __align__(16) float smem[];
    float* sW = smem;               // [128][128] folded weights, 64KB
    float* sX[2] = { smem + 16384, smem + 16384 + XSZ };

    const int g   = blockIdx.x;
    const int tid = threadIdx.x;
    const int cq  = tid & 63;
    const int nq  = tid >> 6;
    const int n0  = ptr[g];
    const float b0 = bag[g * 4 + 0], b1 = bag[g * 4 + 1];
    const float b2 = bag[g * 4 + 2], b3 = bag[g * 4 + 3];
    const float* Wraw = W_bag + (size_t)L * 65536;
    const float* Xg   = s_inter + (size_t)n0 * 1152 + OFF;

    ull acc[2][2][OL];
#pragma unroll
    for (int cc = 0; cc < 2; cc++)
#pragma unroll
        for (int np = 0; np < 2; np++)
#pragma unroll
            for (int m = 0; m < OL; m++) acc[cc][np][m] = 0ull;

    // thread's fixed (node, j) coordinates for X staging
    const int xnl = tid / XCH;            // may be >= 20 for L=0 (tid>=320? no, 320/16=20 exact)
    const int xj  = tid - xnl * XCH;

    float xr[2][NPT];

    // ---- X chunk -> regs (set S) ----
#define LDX(C, S)                                                           \
    {                                                                       \
        const float* src = Xg + (C) * XCH;                                  \
        _Pragma("unroll")                                                   \
        for (int t = 0; t < NPT; t++) {                                     \
            const int idx = tid + t * 320;                                  \
            const int nl = idx / XCH;                                       \
            const int j  = idx - nl * XCH;                                  \
            xr[S][t] = src[(size_t)nl * 1152 + j];                          \
        }                                                                   \
    }
    // ---- X regs (set S) -> smem buffer B (transposed) ----
#define STX(B, S)                                                           \
    {                                                                       \
        _Pragma("unroll")                                                   \
        for (int t = 0; t < NPT; t++) {                                     \
            const int idx = tid + t * 320;                                  \
            const int nl = idx / XCH;                                       \
            const int j  = idx - nl * XCH;                                  \
            (B)[j * 20 + nl] = xr[S][t];                                    \
        }                                                                   \
    }

    // ---- preamble: X(0), X(1) in flight; fold W under their latency ----
    LDX(0, 0);
    LDX(1, 1);

    // fold the ENTIRE W_eff into SMEM once (W_bag is L2-resident)
#pragma unroll 2
    for (int t = tid; t < 4096; t += 320) {
        const int ii = t >> 5, o4 = (t & 31) << 2;
        const float* wp = Wraw + (size_t)ii * 512 + o4;
        const float4 w0 = *reinterpret_cast<const float4*>(wp);
        const float4 w1 = *reinterpret_cast<const float4*>(wp + 128);
        const float4 w2 = *reinterpret_cast<const float4*>(wp + 256);
        const float4 w3 = *reinterpret_cast<const float4*>(wp + 384);
        float4 r;
        r.x = fmaf(b0, w0.x, fmaf(b1, w1.x, fmaf(b2, w2.x, b3 * w3.x)));
        r.y = fmaf(b0, w0.y, fmaf(b1, w1.y, fmaf(b2, w2.y, b3 * w3.y)));
        r.z = fmaf(b0, w0.z, fmaf(b1, w1.z, fmaf(b2, w2.z, b3 * w3.z)));
        r.w = fmaf(b0, w0.w, fmaf(b1, w1.w, fmaf(b2, w2.w, b3 * w3.w)));
        *reinterpret_cast<float4*>(sW + ii * 128 + o4) = r;
    }

    STX(sX[0], 0);        // chunk 0 -> buf 0
    __syncthreads();      // sW + sX[0] visible

    // ---- main loop: ONE barrier per chunk, 2-deep X prefetch ----
    // invariant at iter c: chunk c in sX[c&1]; chunk c+1 in xr[(c+1)&1]
#pragma unroll
    for (int c = 0; c < 8; c++) {
        if (c + 2 < 8) LDX(c + 2, c & 1);            // overwrites chunk-c regs (already staged)
        k1_compute<OL>(sW + c * 16 * 128, sX[c & 1], cq, nq, acc);
        if (c + 1 < 8) {
            STX(sX[(c + 1) & 1], (c + 1) & 1);       // disjoint from compute's buffer
            __syncthreads();
        }
    }

#undef LDX
#undef STX

    // ---- epilogue: norms for all (n,o); cov for focused node ----
    const int foc = focus[g];
#pragma unroll
    for (int cc = 0; cc < 2; cc++) {
        const int col = cq * 2 + cc;
#pragma unroll
        for (int np = 0; np < 2; np++) {
            const int nloc = nq * 4 + np * 2;
            float s0 = 1e-12f, s1 = 1e-12f;
            float lo[OL], hi[OL];
#pragma unroll
            for (int m = 0; m < OL; m++) {
                float l, h;
                upk2(acc[cc][np][m], l, h);
                l *= INV_SQMZ; h *= INV_SQMZ;
                s0 = fmaf(l, l, s0); s1 = fmaf(h, h, s1);
                lo[m] = l; hi[m] = h;
            }
            const int na = n0 + nloc;
            g_sinv[(size_t)na * 384 + L * 128 + col]       = sqrtf(s0);
            g_sinv[(size_t)(na + 1) * 384 + L * 128 + col] = sqrtf(s1);
            if (nloc == foc) {
#pragma unroll
                for (int m = 0; m < OL; m++)
                    g_scov[(size_t)g * 1152 + OFF + col * OL + m] = lo[m];
            }
            if (nloc + 1 == foc) {
#pragma unroll
                for (int m = 0; m < OL; m++)
                    g_scov[(size_t)g * 1152 + OFF + col * OL + m] = hi[m];
            }
        }
    }
}

// ---------------- K2: fused focus + element MLPs ----------------
__global__ void __launch_bounds__(128, 4) k2_mlp(
    const float* __restrict__ gW1f, const float* __restrict__ gb1f,
    const float* __restrict__ gW2f, const float* __restrict__ gb2f,
    const float* __restrict__ gW1e, const float* __restrict__ gb1e,
    const float* __restrict__ gW2e, const float* __restrict__ gb2e)
{
    __shared__ __align__(16) float sS[384 * 32];     // [k][nn]
    const int tid = threadIdx.x;
    const int nb  = blockIdx.x * 32;
    for (int e = tid; e < 96 * 32; e += 128) {
        const int kq = e >> 5, nn = e & 31;
        const int nglob = nb + nn;
        float4 v = make_float4(0.f, 0.f, 0.f, 0.f);
        if (nglob < NN_)
            v = *reinterpret_cast<const float4*>(g_sinv + (size_t)nglob * 384 + kq * 4);
        sS[(kq * 4 + 0) * 32 + nn] = v.x;
        sS[(kq * 4 + 1) * 32 + nn] = v.y;
        sS[(kq * 4 + 2) * 32 + nn] = v.z;
        sS[(kq * 4 + 3) * 32 + nn] = v.w;
    }
    __syncthreads();

    const float bf = gb1f[tid], be = gb1e[tid];
    ull acc2f[16], acc2e[16];
#pragma unroll
    for (int p = 0; p < 16; p++) { acc2f[p] = pk2(bf, bf); acc2e[p] = pk2(be, be); }

    for (int k0 = 0; k0 < 384; k0 += 4) {
        float wf[4], we[4];
#pragma unroll
        for (int q = 0; q < 4; q++) {
            wf[q] = gW1f[(k0 + q) * 128 + tid];
            we[q] = gW1e[(k0 + q) * 128 + tid];
        }
#pragma unroll
        for (int q = 0; q < 4; q++) {
            const ull wf2 = pk2(wf[q], wf[q]);
            const ull we2 = pk2(we[q], we[q]);
            const ulonglong2* x2 = reinterpret_cast<const ulonglong2*>(sS + (k0 + q) * 32);
#pragma unroll
            for (int p8 = 0; p8 < 8; p8++) {
                const ulonglong2 xx = x2[p8];
                fma2_(acc2f[p8 * 2 + 0], wf2, xx.x);
                fma2_(acc2f[p8 * 2 + 1], wf2, xx.y);
                fma2_(acc2e[p8 * 2 + 0], we2, xx.x);
                fma2_(acc2e[p8 * 2 + 1], we2, xx.y);
            }
        }
    }

    float accf[32], acce[32];
#pragma unroll
    for (int p = 0; p < 16; p++) {
        upk2(acc2f[p], accf[2 * p], accf[2 * p + 1]);
        upk2(acc2e[p], acce[2 * p], acce[2 * p + 1]);
    }

    const float w2f = gW2f[tid];
    float w2e[4];
#pragma unroll
    for (int z = 0; z < 4; z++) w2e[z] = gW2e[tid * 4 + z];
    const int lane = tid & 31, wid = tid >> 5;
    __syncthreads();
    float* sR = sS;
    for (int nn = 0; nn < 32; nn++) {
        const float hf = fmaxf(accf[nn], 0.f);
        const float he = fmaxf(acce[nn], 0.f);
        float v0 = hf * w2f, v1 = he * w2e[0], v2 = he * w2e[1],
              v3 = he * w2e[2], v4 = he * w2e[3];
#pragma unroll
        for (int s = 16; s > 0; s >>= 1) {
            v0 += __shfl_down_sync(0xffffffffu, v0, s);
            v1 += __shfl_down_sync(0xffffffffu, v1, s);
            v2 += __shfl_down_sync(0xffffffffu, v2, s);
            v3 += __shfl_down_sync(0xffffffffu, v3, s);
            v4 += __shfl_down_sync(0xffffffffu, v4, s);
        }
        if (lane == 0) {
            const int base = (wid * 32 + nn) * 5;
            sR[base + 0] = v0; sR[base + 1] = v1; sR[base + 2] = v2;
            sR[base + 3] = v3; sR[base + 4] = v4;
        }
    }
    __syncthreads();
    if (tid < 32) {
        const int nglob = nb + tid;
        if (nglob < NN_) {
            float f = gb2f[0];
#pragma unroll
            for (int w = 0; w < 4; w++) f += sR[(w * 32 + tid) * 5 + 0];
            g_fl[nglob] = f;
#pragma unroll
            for (int z = 0; z < 4; z++) {
                float e = gb2e[z];
#pragma unroll
                for (int w = 0; w < 4; w++) e += sR[(w * 32 + tid) * 5 + 1 + z];
                g_el[(size_t)nglob * 4 + z] = e;
            }
        }
    }
}

// ---------------- K3: group softmaxes / entropies ----------------
__global__ void __launch_bounds__(128) k3_group(
    const float* __restrict__ bag, const int* __restrict__ ptr,
    const int* __restrict__ focus, const int* __restrict__ element,
    float* __restrict__ out)
{
    const int g = blockIdx.x * 4 + (threadIdx.x >> 5);
    const int lane = threadIdx.x & 31;
    if (g >= GG_) return;
    const int n0 = ptr[g];
    const int cnt = ptr[g + 1] - n0;
    const int foc = focus[g];
    const int zel = element[g];
    const bool valid = lane < cnt;
    const int n = n0 + lane;
    float f = valid ? g_fl[n] : -3.0e38f;
    float mx = f;
#pragma unroll
    for (int s = 16; s > 0; s >>= 1) mx = fmaxf(mx, __shfl_xor_sync(0xffffffffu, mx, s));
    const float ex = valid ? expf(f - mx) : 0.f;
    const float S  = wsum(ex);
    const float fp = ex / S;
    const float hfocus = wsum(valid ? -fp * logf(fp + 1e-20f) : 0.f);
    float hel = 0.f, pzel = 0.f;
    if (valid) {
        float lz[4];
        float m4 = -3.0e38f;
#pragma unroll
        for (int z = 0; z < 4; z++) {
            float v = g_el[(size_t)n * 4 + z];
            v = (bag[g * 4 + z] > 0.f) ? v : -1e9f;
            lz[z] = v; m4 = fmaxf(m4, v);
        }
        float s4 = 0.f;
#pragma unroll
        for (int z = 0; z < 4; z++) { lz[z] = expf(lz[z] - m4); s4 += lz[z]; }
#pragma unroll
        for (int z = 0; z < 4; z++) {
            lz[z] /= s4;
            hel -= lz[z] * logf(fmaxf(lz[z], 1e-20f));
        }
        pzel = lz[zel];
    }
    const float hef = wsum(fp * hel);
    const float lp = wsum((valid && lane == foc)
                          ? (logf(fp + 1e-20f) + logf(pzel + 1e-20f)) : 0.f);
    if (lane == 0) { g_lp12[g] = lp; out[2 * g + 1] = hfocus + hef; }
}

// ---------------- K5: distance MLP/GMM + cond + orientation logZ ----------------
__global__ void __launch_bounds__(128) k5_final(
    const int* __restrict__ ptr, const int* __restrict__ focus,
    const int* __restrict__ element, const float* __restrict__ distance,
    const float* __restrict__ orientation,
    const float* __restrict__ W1d, const float* __restrict__ b1d,
    const float* __restrict__ W2d, const float* __restrict__ b2d,
    const float* __restrict__ d_log_stds, float* __restrict__ out)
{
    const int tid = threadIdx.x, lane = tid & 31, wq = tid >> 5;
    const int gbase = blockIdx.x * 4;
    __shared__ float sSI[4][384];
    __shared__ int   sGI[4], sEl[4];
    __shared__ float sRed[4][4][6];
    if (tid < 4) {
        const int g = gbase + tid;
        sGI[tid] = (g < GG_) ? (ptr[g] + focus[g]) : 0;
        sEl[tid] = (g < GG_) ? element[g] : 0;
    }
    __syncthreads();
#pragma unroll
    for (int q = 0; q < 4; q++)
        for (int k = tid; k < 384; k += 128)
            sSI[q][k] = g_sinv[(size_t)sGI[q] * 384 + k];
    __syncthreads();

    float acc[4];
    const float b1 = b1d[tid];
#pragma unroll
    for (int q = 0; q < 4; q++) acc[q] = b1;
    for (int k = 0; k < 384; k++) {
        const float w = W1d[k * 128 + tid];
#pragma unroll
        for (int q = 0; q < 4; q++) acc[q] = fmaf(w, sSI[q][k], acc[q]);
    }
#pragma unroll
    for (int q = 0; q < 4; q++) acc[q] += W1d[(384 + sEl[q]) * 128 + tid];

    float w2[6];
#pragma unroll
    for (int j = 0; j < 6; j++) w2[j] = W2d[tid * 6 + j];
#pragma unroll
    for (int q = 0; q < 4; q++) {
        const float h = fmaxf(acc[q], 0.f);
        float v[6];
#pragma unroll
        for (int j = 0; j < 6; j++) v[j] = h * w2[j];
#pragma unroll
        for (int s = 16; s > 0; s >>= 1)
#pragma unroll
            for (int j = 0; j < 6; j++) v[j] += __shfl_down_sync(0xffffffffu, v[j], s);
        if (lane == 0)
#pragma unroll
            for (int j = 0; j < 6; j++) sRed[wq][q][j] = v[j];
    }
    __syncthreads();

    const int g = gbase + wq;
    if (g >= GG_) return;
    float hj[6];
#pragma unroll
    for (int j = 0; j < 6; j++)
        hj[j] = sRed[0][wq][j] + sRed[1][wq][j] + sRed[2][wq][j] + sRed[3][wq][j] + b2d[j];

    const float d = distance[g];
    float lm = fmaxf(hj[0], fmaxf(hj[1], hj[2]));
    float se = expf(hj[0] - lm) + expf(hj[1] - lm) + expf(hj[2] - lm);
    const float lse = lm + logf(se);
    float aj[3];
#pragma unroll
    for (int j = 0; j < 3; j++) {
        const float mean = tanhf(hj[3 + j]) * 0.45f + 1.35f;
        const float std  = fmaxf(expf(d_log_stds[j]), 1e-6f);
        const float t = (d - mean) / std;
        aj[j] = (hj[j] - lse) - 0.5f * t * t - logf(std) - 0.91893853320467274f;
    }
    float am = fmaxf(aj[0], fmaxf(aj[1], aj[2]));
    const float lp_dist = am + logf(expf(aj[0] - am) + expf(aj[1] - am) + expf(aj[2] - am));

    float bess[8];
#pragma unroll
    for (int k = 0; k < 8; k++)
        bess[k] = 1.0540925533894598f * sinf((float)(k + 1) * 3.14159265358979f * d / 1.8f) / d;

    const int zel = sEl[wq];
    float cond[9];
#pragma unroll
    for (int j = 0; j < 9; j++) cond[j] = 0.f;
    const float* scov = g_scov + (size_t)g * 1152;
#pragma unroll
    for (int ib = 0; ib < 4; ib++) {
        const int i = lane + ib * 32;
        // transposed W_mix: [zel][l][i][k], 8 consecutive k
        {
            const float* wt = g_wmixT + ((zel * 3 + 0) * 128 + i) * 8;
            const float4 wa = *reinterpret_cast<const float4*>(wt);
            const float4 wb = *reinterpret_cast<const float4*>(wt + 4);
            float tw = bess[0] * wa.x + bess[1] * wa.y + bess[2] * wa.z + bess[3] * wa.w
                     + bess[4] * wb.x + bess[5] * wb.y + bess[6] * wb.z + bess[7] * wb.w;
            tw *= 0.3535533905932738f;
            cond[0] = fmaf(scov[i], tw, cond[0]);
        }
        {
            const float* wt = g_wmixT + ((zel * 3 + 1) * 128 + i) * 8;
            const float4 wa = *reinterpret_cast<const float4*>(wt);
            const float4 wb = *reinterpret_cast<const float4*>(wt + 4);
            float tw = bess[0] * wa.x + bess[1] * wa.y + bess[2] * wa.z + bess[3] * wa.w
                     + bess[4] * wb.x + bess[5] * wb.y + bess[6] * wb.z + bess[7] * wb.w;
            tw *= 0.3535533905932738f;
#pragma unroll
            for (int m = 0; m < 3; m++)
                cond[1 + m] = fmaf(scov[128 + i * 3 + m], tw, cond[1 + m]);
        }
        {
            const float* wt = g_wmixT + ((zel * 3 + 2) * 128 + i) * 8;
            const float4 wa = *reinterpret_cast<const float4*>(wt);
            const float4 wb = *reinterpret_cast<const float4*>(wt + 4);
            float tw = bess[0] * wa.x + bess[1] * wa.y + bess[2] * wa.z + bess[3] * wa.w
                     + bess[4] * wb.x + bess[5] * wb.y + bess[6] * wb.z + bess[7] * wb.w;
            tw *= 0.3535533905932738f;
#pragma unroll
            for (int m = 0; m < 5; m++)
                cond[4 + m] = fmaf(scov[512 + i * 5 + m], tw, cond[4 + m]);
        }
    }
#pragma unroll
    for (int j = 0; j < 9; j++) cond[j] = wsum(cond[j]) * INV_SQMZ;

    // grid logsumexp: 4 points per lane per iteration (float4 g_Y reads)
    float m_run = -3.0e38f, s_run = 0.f;
    for (int t = 0; t < 32; t++) {
        const int p0 = t * 128 + lane * 4;
        float4 f4 = make_float4(0.f, 0.f, 0.f, 0.f);
#pragma unroll
        for (int j = 0; j < 9; j++) {
            const float4 y = *reinterpret_cast<const float4*>(g_Y + j * PGRID + p0);
            f4.x = fmaf(cond[j], y.x, f4.x);
            f4.y = fmaf(cond[j], y.y, f4.y);
            f4.z = fmaf(cond[j], y.z, f4.z);
            f4.w = fmaf(cond[j], y.w, f4.w);
        }
        const float fm = fmaxf(fmaxf(f4.x, f4.y), fmaxf(f4.z, f4.w)) * 10.0f;
        const float nm = fmaxf(m_run, fm);
        const float sc = __expf(m_run - nm);
        float sl = __expf(10.0f * f4.x - nm) + __expf(10.0f * f4.y - nm)
                 + __expf(10.0f * f4.z - nm) + __expf(10.0f * f4.w - nm);
        s_run = s_run * sc + sl;
        m_run = nm;
    }
#pragma unroll
    for (int s = 16; s > 0; s >>= 1) {
        const float om = __shfl_xor_sync(0xffffffffu, m_run, s);
        const float os = __shfl_xor_sync(0xffffffffu, s_run, s);
        const float nm = fmaxf(m_run, om);
        s_run = s_run * __expf(m_run - nm) + os * __expf(om - nm);
        m_run = nm;
    }
    const float logZ = m_run + logf(s_run) - 8.317766166719343f + 2.5310242469692907f;

    if (lane == 0) {
        float ox = orientation[g * 3 + 0], oy = orientation[g * 3 + 1],
              oz = orientation[g * 3 + 2];
        const float inv = rsqrtf(ox * ox + oy * oy + oz * oz);
        ox *= inv; oy *= inv; oz *= inv;
        float sh[9];
        sh[0] = 0.28209479177387814f;
        sh[1] = 0.4886025119029199f * oy;
        sh[2] = 0.4886025119029199f * oz;
        sh[3] = 0.4886025119029199f * ox;
        sh[4] = 1.0925484305920792f * ox * oy;
        sh[5] = 1.0925484305920792f * oy * oz;
        sh[6] = 0.31539156525252005f * (3.f * oz * oz - 1.f);
        sh[7] = 1.0925484305920792f * ox * oz;
        sh[8] = 0.5462742152960396f * (ox * ox - oy * oy);
        float f_x = 0.f;
#pragma unroll
        for (int j = 0; j < 9; j++) f_x = fmaf(cond[j], sh[j], f_x);
        const float lp_ori = 10.0f * f_x - logZ;
        out[2 * g] = g_lp12[g] + lp_dist + lp_ori;
    }
}

// ---------------- launch ----------------
extern "C" void kernel_launch(void* const* d_in, const int* in_sizes, int n_in,
                              void* d_out, int out_size) {
    const float* s_inter     = (const float*)d_in[0];
    const float* bag         = (const float*)d_in[1];
    const int*   ptr         = (const int*)  d_in[3];
    const int*   focus       = (const int*)  d_in[4];
    const int*   element     = (const int*)  d_in[5];
    const float* distance    = (const float*)d_in[6];
    const float* orientation = (const float*)d_in[7];
    const float* W_bag       = (const float*)d_in[8];
    const float* d_log_stds  = (const float*)d_in[9];
    const float* W_mix       = (const float*)d_in[10];
    const float* W1f = (const float*)d_in[11];
    const float* b1f = (const float*)d_in[12];
    const float* W2f = (const float*)d_in[13];
    const float* b2f = (const float*)d_in[14];
    const float* W1e = (const float*)d_in[15];
    const float* b1e = (const float*)d_in[16];
    const float* W2e = (const float*)d_in[17];
    const float* b2e = (const float*)d_in[18];
    const float* W1d = (const float*)d_in[19];
    const float* b1d = (const float*)d_in[20];
    const float* W2d = (const float*)d_in[21];
    const float* b2d = (const float*)d_in[22];
    float* out = (float*)d_out;

    const int smem2 = 65536 + 2 * 5 * 16 * 20 * 4;  // 78336
    const int smem1 = 65536 + 2 * 3 * 16 * 20 * 4;  // 73216
    const int smem0 = 65536 + 2 * 1 * 16 * 20 * 4;  // 68096
    cudaFuncSetAttribute(k1_cov<2>, cudaFuncAttributeMaxDynamicSharedMemorySize, smem2);
    cudaFuncSetAttribute(k1_cov<1>, cudaFuncAttributeMaxDynamicSharedMemorySize, smem1);
    cudaFuncSetAttribute(k1_cov<0>, cudaFuncAttributeMaxDynamicSharedMemorySize, smem0);

    k0_ygrid<<<32, 128>>>();
    kt_wmix<<<96, 128>>>(W_mix);
    k1_cov<2><<<GG_, 320, smem2>>>(s_inter, bag, ptr, focus, W_bag);
    k1_cov<1><<<GG_, 320, smem1>>>(s_inter, bag, ptr, focus, W_bag);
    k1_cov<0><<<GG_, 320, smem0>>>(s_inter, bag, ptr, focus, W_bag);
    k2_mlp<<<(NN_ + 31) / 32, 128>>>(W1f, b1f, W2f, b2f, W1e, b1e, W2e, b2e);
    k3_group<<<(GG_ + 3) / 4, 128>>>(bag, ptr, focus, element, out);
    k5_final<<<(GG_ + 3) / 4, 128>>>(ptr, focus, element, distance, orientation,
                                     W1d, b1d, W2d, b2d, d_log_stds, out);
}